// round 1
// baseline (speedup 1.0000x reference)
#include <cuda_runtime.h>
#include <math.h>

#define BB 4
#define TT 2048
#define DD 1024
#define DK 128
#define RR (BB*TT)   // 8192

// Scratch (device globals: allocation-free)
__device__ float g_Q[RR*DK];
__device__ float g_K[RR*DK];
__device__ float g_V[RR*DK];
__device__ float g_O[RR*DK];

// ---------------------------------------------------------------------------
// Generic SGEMM: C[M,N] = A[M,K] @ B[K,N], row-major, all dims multiples of
// tile sizes (M%64==0, N%128==0, K%16==0). 256 threads, 4x8 register tile.
// ---------------------------------------------------------------------------
__global__ __launch_bounds__(256) void gemm_kernel(
    const float* __restrict__ A, const float* __restrict__ Bw,
    float* __restrict__ C, int M, int N, int K)
{
    __shared__ float As[64*16];
    __shared__ float Bs[16*128];
    const int tid = threadIdx.x;
    const int tx = tid & 15, ty = tid >> 4;
    const int m0 = blockIdx.y * 64;
    const int n0 = blockIdx.x * 128;

    float acc[4][8];
#pragma unroll
    for (int r = 0; r < 4; r++)
#pragma unroll
        for (int j = 0; j < 8; j++) acc[r][j] = 0.f;

    for (int k0 = 0; k0 < K; k0 += 16) {
#pragma unroll
        for (int i = 0; i < 4; i++) {          // A tile: 64x16
            int e = tid * 4 + i;
            int r = e >> 4, kk = e & 15;
            As[e] = A[(size_t)(m0 + r) * K + k0 + kk];
        }
#pragma unroll
        for (int i = 0; i < 8; i++) {          // B tile: 16x128
            int e = tid * 8 + i;
            int kk = e >> 7, n = e & 127;
            Bs[e] = Bw[(size_t)(k0 + kk) * N + n0 + n];
        }
        __syncthreads();
#pragma unroll
        for (int kk = 0; kk < 16; kk++) {
            float a[4], b[8];
#pragma unroll
            for (int r = 0; r < 4; r++) a[r] = As[(ty * 4 + r) * 16 + kk];
#pragma unroll
            for (int j = 0; j < 8; j++) b[j] = Bs[kk * 128 + j * 16 + tx];
#pragma unroll
            for (int r = 0; r < 4; r++)
#pragma unroll
                for (int j = 0; j < 8; j++) acc[r][j] += a[r] * b[j];
        }
        __syncthreads();
    }
#pragma unroll
    for (int r = 0; r < 4; r++)
#pragma unroll
        for (int j = 0; j < 8; j++)
            C[(size_t)(m0 + ty * 4 + r) * N + n0 + j * 16 + tx] = acc[r][j];
}

// ---------------------------------------------------------------------------
// Flash attention (causal), BQ=64 rows per block, BKV=64, d=128.
// Grid: (T/64, B). 256 threads as 16x16. Thread tile: 4 rows x (4 S-cols,
// 8 O-cols). K held transposed in smem (stride 68, 16B aligned rows) for
// conflict-free LDS.128 in the S phase. Online softmax across the 16-lane
// row group via shfl_xor.
// ---------------------------------------------------------------------------
#define KT_STRIDE 68
#define FLASH_SMEM_FLOATS (64*128 + 128*KT_STRIDE + 64*128 + 64*64)

__global__ __launch_bounds__(256) void flash_kernel()
{
    extern __shared__ float sm[];
    float* Qs = sm;                         // 64*128
    float* Kt = Qs + 64 * 128;              // 128*68 (K transposed: Kt[d][c])
    float* Vs = Kt + 128 * KT_STRIDE;       // 64*128
    float* Ps = Vs + 64 * 128;              // 64*64

    const int tid = threadIdx.x;
    const int tx = tid & 15, ty = tid >> 4;
    const int qt = blockIdx.x;              // query tile index (0..31)
    const int b  = blockIdx.y;
    const int q0 = qt * 64;

    const float* Qg = g_Q + (size_t)(b * TT + q0) * DK;
    const float* Kg = g_K + (size_t)b * TT * DK;
    const float* Vg = g_V + (size_t)b * TT * DK;

    // Load Q tile (coalesced)
#pragma unroll
    for (int i = 0; i < 32; i++) {
        int e = i * 256 + tid;
        Qs[e] = Qg[e];
    }

    float m[4], l[4], acc[4][8];
#pragma unroll
    for (int r = 0; r < 4; r++) { m[r] = -1e30f; l[r] = 0.f; }
#pragma unroll
    for (int r = 0; r < 4; r++)
#pragma unroll
        for (int j = 0; j < 8; j++) acc[r][j] = 0.f;

    const float scale = 0.08838834764831845f;   // 1/sqrt(128)

    for (int j = 0; j <= qt; j++) {
        __syncthreads();   // prev iter's Ps/Vs/Kt reads done (also covers Qs load)

        // Load K tile transposed + V tile straight
        const float* Kj = Kg + (size_t)j * 64 * DK;
        const float* Vj = Vg + (size_t)j * 64 * DK;
#pragma unroll
        for (int i = 0; i < 32; i++) {
            int e = i * 256 + tid;
            int c = e >> 7, d = e & 127;
            Kt[d * KT_STRIDE + c] = Kj[e];
            Vs[e] = Vj[e];
        }
        __syncthreads();

        // --- S = Q K^T (4x4 per thread) ---
        float S[4][4];
#pragma unroll
        for (int r = 0; r < 4; r++)
#pragma unroll
            for (int cc = 0; cc < 4; cc++) S[r][cc] = 0.f;

        for (int d0 = 0; d0 < 128; d0 += 4) {
            float4 kv[4];
#pragma unroll
            for (int t = 0; t < 4; t++)
                kv[t] = *(const float4*)&Kt[(d0 + t) * KT_STRIDE + tx * 4];
#pragma unroll
            for (int r = 0; r < 4; r++) {
                float4 q4 = *(const float4*)&Qs[(ty * 4 + r) * 128 + d0];
                S[r][0] += q4.x*kv[0].x + q4.y*kv[1].x + q4.z*kv[2].x + q4.w*kv[3].x;
                S[r][1] += q4.x*kv[0].y + q4.y*kv[1].y + q4.z*kv[2].y + q4.w*kv[3].y;
                S[r][2] += q4.x*kv[0].z + q4.y*kv[1].z + q4.z*kv[2].z + q4.w*kv[3].z;
                S[r][3] += q4.x*kv[0].w + q4.y*kv[1].w + q4.z*kv[2].w + q4.w*kv[3].w;
            }
        }

        // scale + causal mask (only the diagonal tile needs it)
#pragma unroll
        for (int r = 0; r < 4; r++)
#pragma unroll
            for (int cc = 0; cc < 4; cc++) S[r][cc] *= scale;
        if (j == qt) {
#pragma unroll
            for (int r = 0; r < 4; r++) {
                int row = q0 + ty * 4 + r;
#pragma unroll
                for (int cc = 0; cc < 4; cc++) {
                    int col = j * 64 + tx * 4 + cc;
                    if (col > row) S[r][cc] = -1e30f;
                }
            }
        }

        // --- online softmax, P -> smem ---
#pragma unroll
        for (int r = 0; r < 4; r++) {
            float mt = fmaxf(fmaxf(S[r][0], S[r][1]), fmaxf(S[r][2], S[r][3]));
#pragma unroll
            for (int off = 1; off < 16; off <<= 1)
                mt = fmaxf(mt, __shfl_xor_sync(0xffffffffu, mt, off));
            float mn = fmaxf(m[r], mt);
            float alpha = __expf(m[r] - mn);
            float p0 = __expf(S[r][0] - mn);
            float p1 = __expf(S[r][1] - mn);
            float p2 = __expf(S[r][2] - mn);
            float p3 = __expf(S[r][3] - mn);
            float lt = (p0 + p1) + (p2 + p3);
#pragma unroll
            for (int off = 1; off < 16; off <<= 1)
                lt += __shfl_xor_sync(0xffffffffu, lt, off);
            l[r] = l[r] * alpha + lt;
            m[r] = mn;
#pragma unroll
            for (int jj = 0; jj < 8; jj++) acc[r][jj] *= alpha;
            float* pr = &Ps[(ty * 4 + r) * 64 + tx * 4];
            pr[0] = p0; pr[1] = p1; pr[2] = p2; pr[3] = p3;
        }
        __syncthreads();

        // --- O += P V ---
        for (int c = 0; c < 64; c++) {
            float p[4], v[8];
#pragma unroll
            for (int r = 0; r < 4; r++) p[r] = Ps[(ty * 4 + r) * 64 + c];
#pragma unroll
            for (int jj = 0; jj < 8; jj++) v[jj] = Vs[c * 128 + jj * 16 + tx];
#pragma unroll
            for (int r = 0; r < 4; r++)
#pragma unroll
                for (int jj = 0; jj < 8; jj++) acc[r][jj] += p[r] * v[jj];
        }
    }

    // epilogue: normalize and store O
#pragma unroll
    for (int r = 0; r < 4; r++) {
        float inv = 1.f / l[r];
        int row = b * TT + q0 + ty * 4 + r;
#pragma unroll
        for (int jj = 0; jj < 8; jj++)
            g_O[(size_t)row * DK + jj * 16 + tx] = acc[r][jj] * inv;
    }
}

// ---------------------------------------------------------------------------
extern "C" void kernel_launch(void* const* d_in, const int* in_sizes, int n_in,
                              void* d_out, int out_size)
{
    const float* x  = (const float*)d_in[0];
    const float* Wq = (const float*)d_in[1];
    const float* Wk = (const float*)d_in[2];
    const float* Wv = (const float*)d_in[3];
    const float* Wo = (const float*)d_in[4];
    float* out = (float*)d_out;

    float *gq, *gk, *gv, *go;
    cudaGetSymbolAddress((void**)&gq, g_Q);
    cudaGetSymbolAddress((void**)&gk, g_K);
    cudaGetSymbolAddress((void**)&gv, g_V);
    cudaGetSymbolAddress((void**)&go, g_O);

    const int flash_smem = FLASH_SMEM_FLOATS * (int)sizeof(float);  // 116736 B
    cudaFuncSetAttribute(flash_kernel,
                         cudaFuncAttributeMaxDynamicSharedMemorySize, flash_smem);

    dim3 blk(256);
    // Q/K/V projections: [8192,1024] @ [1024,128]
    gemm_kernel<<<dim3(1, RR / 64), blk>>>(x, Wq, gq, RR, DK, DD);
    gemm_kernel<<<dim3(1, RR / 64), blk>>>(x, Wk, gk, RR, DK, DD);
    gemm_kernel<<<dim3(1, RR / 64), blk>>>(x, Wv, gv, RR, DK, DD);

    // Causal flash attention
    flash_kernel<<<dim3(TT / 64, BB), blk, flash_smem>>>();

    // Output projection: [8192,128] @ [128,1024]
    gemm_kernel<<<dim3(DD / 128, RR / 64), blk>>>(go, Wo, out, RR, DD, DK);
}